// round 3
// baseline (speedup 1.0000x reference)
#include <cuda_runtime.h>
#include <cuda_bf16.h>
#include <stdint.h>

#define DEV __device__ __forceinline__

namespace {
constexpr int BATCH = 4096;
constexpr int NROW  = 8192;   // 2B rows
constexpr int DIM   = 128;
constexpr int TILES = 32;     // 4096 cols per split / 128-col tiles
constexpr int SA    = 136;    // padded smem stride (bf16 elems): conflict-free frags
constexpr unsigned SMEM_BYTES = 2u * 128u * SA * 2u;   // A + B tiles (bf16)
// prescale: sqrt(10 * log2(e))  -> MMA output = sim * (1/T) * log2(e)  (base-2 logits)
constexpr float PRESCALE = 3.79828310f;
}

// scratch (device globals: no allocations allowed)
__device__ __align__(256) __nv_bfloat16 g_xn[NROW * DIM];
__device__ float g_m[2][NROW];
__device__ float g_s[2][NROW];
__device__ float g_pair[NROW];

// ---------------- helpers ----------------
DEV float ex2f(float x) { float y; asm("ex2.approx.f32 %0, %1;" : "=f"(y) : "f"(x)); return y; }
DEV float lg2f(float x) { float y; asm("lg2.approx.f32 %0, %1;" : "=f"(y) : "f"(x)); return y; }

DEV void mma16816(float* d, const uint32_t* a, const uint32_t* b) {
    asm volatile(
        "mma.sync.aligned.m16n8k16.row.col.f32.bf16.bf16.f32 "
        "{%0,%1,%2,%3}, {%4,%5,%6,%7}, {%8,%9}, {%0,%1,%2,%3};"
        : "+f"(d[0]), "+f"(d[1]), "+f"(d[2]), "+f"(d[3])
        : "r"(a[0]), "r"(a[1]), "r"(a[2]), "r"(a[3]), "r"(b[0]), "r"(b[1]));
}

// ---------------- kernel 1: normalize + prescale + bf16 ----------------
__global__ void k_norm(const float* __restrict__ o1, const float* __restrict__ o2) {
    int row  = blockIdx.x * 8 + (threadIdx.x >> 5);
    int lane = threadIdx.x & 31;
    const float* src = (row < BATCH) ? (o1 + (size_t)row * DIM)
                                     : (o2 + (size_t)(row - BATCH) * DIM);
    float4 v = reinterpret_cast<const float4*>(src)[lane];
    float ss = v.x * v.x + v.y * v.y + v.z * v.z + v.w * v.w;
#pragma unroll
    for (int o = 16; o; o >>= 1) ss += __shfl_xor_sync(~0u, ss, o);
    float sc = rsqrtf(ss) * PRESCALE;
    __nv_bfloat162 p0 = __floats2bfloat162_rn(v.x * sc, v.y * sc);
    __nv_bfloat162 p1 = __floats2bfloat162_rn(v.z * sc, v.w * sc);
    uint2 u;
    u.x = *reinterpret_cast<uint32_t*>(&p0);
    u.y = *reinterpret_cast<uint32_t*>(&p1);
    reinterpret_cast<uint2*>(&g_xn[(size_t)row * DIM])[lane] = u;
}

// ---------------- kernel 2: tiled Gram (mma.sync) + online base-2 softmax ----------------
__global__ void __launch_bounds__(256, 1) k_sim() {
    extern __shared__ char smem[];
    __nv_bfloat16* sA = reinterpret_cast<__nv_bfloat16*>(smem);
    __nv_bfloat16* sB = sA + 128 * SA;

    const int tid  = threadIdx.x;
    const int wid  = tid >> 5;
    const int lane = tid & 31;
    const int warp_m = wid & 3;        // 4 row groups of 32 rows
    const int warp_n = wid >> 2;       // 2 col halves of 64 cols
    const int cs  = blockIdx.x;        // column split 0/1
    const int rowBase = blockIdx.y * 128;
    const int colSplitBase = cs * 4096;

    // --- load A tile (128 rows x 128 k) and B tile 0 into smem ---
#pragma unroll
    for (int i = 0; i < 8; i++) {
        int idx = tid + i * 256;
        int r   = idx >> 4;
        int kc  = (idx & 15) << 3;
        uint4 va = *reinterpret_cast<const uint4*>(&g_xn[(rowBase + r) * DIM + kc]);
        *reinterpret_cast<uint4*>(&sA[r * SA + kc]) = va;
        uint4 vb = *reinterpret_cast<const uint4*>(&g_xn[(colSplitBase + r) * DIM + kc]);
        *reinterpret_cast<uint4*>(&sB[r * SA + kc]) = vb;
    }
    __syncthreads();

    const int qr = lane >> 2;              // 0..7
    const int qc = (lane & 3) * 2;         // 0,2,4,6

    // online softmax state: 4 rows per thread (i in 0..1, halves +0/+8)
    const float NEG_INF = __int_as_float(0xff800000);
    float m[4] = {NEG_INF, NEG_INF, NEG_INF, NEG_INF};
    float s[4] = {0.f, 0.f, 0.f, 0.f};

    for (int t = 0; t < TILES; t++) {
        // prefetch next B tile into registers (hidden under compute)
        uint4 nx[8];
        if (t + 1 < TILES) {
#pragma unroll
            for (int i = 0; i < 8; i++) {
                int idx = tid + i * 256;
                int r   = idx >> 4;
                int kc  = (idx & 15) << 3;
                nx[i] = *reinterpret_cast<const uint4*>(
                    &g_xn[(colSplitBase + (t + 1) * 128 + r) * DIM + kc]);
            }
        }

        // --- 128x128 tile GEMM: acc[i][j][4], i=mtile(2), j=ntile(8) ---
        float acc[2][8][4];
#pragma unroll
        for (int i = 0; i < 2; i++)
#pragma unroll
            for (int j = 0; j < 8; j++)
#pragma unroll
                for (int c = 0; c < 4; c++) acc[i][j][c] = 0.f;

#pragma unroll
        for (int ks = 0; ks < 8; ks++) {
            const int k0 = ks * 16 + qc;
            uint32_t a[2][4], b[8][2];
#pragma unroll
            for (int i = 0; i < 2; i++) {
                const int r = warp_m * 32 + i * 16 + qr;
                a[i][0] = *reinterpret_cast<const uint32_t*>(&sA[r * SA + k0]);
                a[i][1] = *reinterpret_cast<const uint32_t*>(&sA[(r + 8) * SA + k0]);
                a[i][2] = *reinterpret_cast<const uint32_t*>(&sA[r * SA + k0 + 8]);
                a[i][3] = *reinterpret_cast<const uint32_t*>(&sA[(r + 8) * SA + k0 + 8]);
            }
#pragma unroll
            for (int j = 0; j < 8; j++) {
                const int n = warp_n * 64 + j * 8 + qr;
                b[j][0] = *reinterpret_cast<const uint32_t*>(&sB[n * SA + k0]);
                b[j][1] = *reinterpret_cast<const uint32_t*>(&sB[n * SA + k0 + 8]);
            }
#pragma unroll
            for (int i = 0; i < 2; i++)
#pragma unroll
                for (int j = 0; j < 8; j++)
                    mma16816(acc[i][j], a[i], b[j]);
        }

        // --- epilogue: online base-2 softmax over this tile's columns ---
        const int  colT  = colSplitBase + t * 128;
        const bool diagT = (colT == rowBase);
        const bool pairT = (colT == (rowBase ^ 4096));

#pragma unroll
        for (int i = 0; i < 2; i++) {
#pragma unroll
            for (int h = 0; h < 2; h++) {
                const int ridx = i * 2 + h;
                const int rloc = warp_m * 32 + i * 16 + h * 8 + qr;
                const int grow = rowBase + rloc;

                float v[16];
#pragma unroll
                for (int j = 0; j < 8; j++) {
                    v[j * 2 + 0] = acc[i][j][h * 2 + 0];
                    v[j * 2 + 1] = acc[i][j][h * 2 + 1];
                }

                if (pairT) {
                    const int tgt = (grow ^ 4096) - colT - warp_n * 64 - qc;
                    // thread's cols: warp_n*64 + j*8 + qc + {0,1}
#pragma unroll
                    for (int j = 0; j < 8; j++) {
                        if (tgt == j * 8)     g_pair[grow] = v[j * 2 + 0];
                        if (tgt == j * 8 + 1) g_pair[grow] = v[j * 2 + 1];
                    }
                }
                if (diagT) {
                    const int tgt = rloc - warp_n * 64 - qc;
#pragma unroll
                    for (int j = 0; j < 8; j++) {
                        if (tgt == j * 8)     v[j * 2 + 0] = NEG_INF;
                        if (tgt == j * 8 + 1) v[j * 2 + 1] = NEG_INF;
                    }
                }

                // tile max over thread's 16 + quad (same-row lanes) reduce
                float cm = v[0];
#pragma unroll
                for (int j = 1; j < 16; j++) cm = fmaxf(cm, v[j]);
                cm = fmaxf(cm, __shfl_xor_sync(~0u, cm, 1));
                cm = fmaxf(cm, __shfl_xor_sync(~0u, cm, 2));
                const float mn = fmaxf(m[ridx], cm);

                float a0 = 0.f, a1 = 0.f, a2 = 0.f, a3 = 0.f;
#pragma unroll
                for (int j = 0; j < 16; j += 4) {
                    a0 += ex2f(v[j + 0] - mn);
                    a1 += ex2f(v[j + 1] - mn);
                    a2 += ex2f(v[j + 2] - mn);
                    a3 += ex2f(v[j + 3] - mn);
                }
                float q = (a0 + a1) + (a2 + a3);
                q += __shfl_xor_sync(~0u, q, 1);
                q += __shfl_xor_sync(~0u, q, 2);
                s[ridx] = s[ridx] * ex2f(m[ridx] - mn) + q;
                m[ridx] = mn;
            }
        }

        // --- rotate B buffer ---
        __syncthreads();
        if (t + 1 < TILES) {
#pragma unroll
            for (int i = 0; i < 8; i++) {
                int idx = tid + i * 256;
                int r   = idx >> 4;
                int kc  = (idx & 15) << 3;
                *reinterpret_cast<uint4*>(&sB[r * SA + kc]) = nx[i];
            }
        }
        __syncthreads();
    }

    // --- merge the two column halves per row (via smem, reusing A region) ---
    float* smrg = reinterpret_cast<float*>(smem);   // [2][128] m, then [2][128] s
    __syncthreads();
    if ((lane & 3) == 0) {
#pragma unroll
        for (int ridx = 0; ridx < 4; ridx++) {
            const int i = ridx >> 1, h = ridx & 1;
            const int rloc = warp_m * 32 + i * 16 + h * 8 + qr;
            smrg[warp_n * 128 + rloc]       = m[ridx];
            smrg[256 + warp_n * 128 + rloc] = s[ridx];
        }
    }
    __syncthreads();
    if (tid < 128) {
        float m0 = smrg[tid], m1 = smrg[128 + tid];
        float s0 = smrg[256 + tid], s1 = smrg[384 + tid];
        float mm = fmaxf(m0, m1);
        float sm = s0 * ex2f(m0 - mm) + s1 * ex2f(m1 - mm);
        g_m[cs][rowBase + tid] = mm;
        g_s[cs][rowBase + tid] = sm;
    }
}

// ---------------- kernel 3: merge splits + reduce ----------------
__global__ void k_final(float* out) {
    __shared__ float red[32];
    const int tid = threadIdx.x;
    float acc = 0.f;
    for (int r = tid; r < NROW; r += 1024) {
        float m0 = g_m[0][r], m1 = g_m[1][r];
        float mm = fmaxf(m0, m1);
        float sv = g_s[0][r] * ex2f(m0 - mm) + g_s[1][r] * ex2f(m1 - mm);
        acc += mm + lg2f(sv) - g_pair[r];   // pos_r in base-2 units
    }
#pragma unroll
    for (int o = 16; o; o >>= 1) acc += __shfl_xor_sync(~0u, acc, o);
    if ((tid & 31) == 0) red[tid >> 5] = acc;
    __syncthreads();
    if (tid < 32) {
        float a = red[tid];
#pragma unroll
        for (int o = 16; o; o >>= 1) a += __shfl_xor_sync(~0u, a, o);
        if (tid == 0) out[0] = a * (0.6931471805599453f * 2048.0f); // ln2 * B/2
    }
}

// ---------------- launch ----------------
extern "C" void kernel_launch(void* const* d_in, const int* in_sizes, int n_in,
                              void* d_out, int out_size) {
    (void)in_sizes; (void)n_in; (void)out_size;
    const float* o1 = (const float*)d_in[0];
    const float* o2 = (const float*)d_in[1];

    k_norm<<<NROW / 8, 256>>>(o1, o2);

    static bool attr_set = false;
    if (!attr_set) {
        cudaFuncSetAttribute(k_sim, cudaFuncAttributeMaxDynamicSharedMemorySize, SMEM_BYTES);
        attr_set = true;
    }
    dim3 grid(2, 64);
    k_sim<<<grid, 256, SMEM_BYTES>>>();

    k_final<<<1, 1024>>>((float*)d_out);
}

// round 4
// speedup vs baseline: 1.1208x; 1.1208x over previous
#include <cuda_runtime.h>
#include <cuda_bf16.h>
#include <stdint.h>

#define DEV __device__ __forceinline__

namespace {
constexpr int BATCH = 4096;
constexpr int NROW  = 8192;   // 2B rows
constexpr int DIM   = 128;
constexpr int TILES = 32;     // 4096 cols per split / 128-col tiles
constexpr int SA    = 136;    // padded smem stride (bf16): conflict-free ldmatrix
constexpr unsigned TILE_BYTES_SM = 128u * SA * 2u;            // 34816
constexpr unsigned SMEM_BYTES    = 3u * TILE_BYTES_SM;        // A + B0 + B1
// prescale: sqrt((1/T) * log2(e)) -> MMA output directly = base-2 logits
constexpr float PRESCALE = 3.79828310f;
}

// scratch (device globals: no allocations allowed)
__device__ __align__(256) __nv_bfloat16 g_xn[NROW * DIM];
__device__ float g_s[2][NROW];
__device__ float g_pair[NROW];

// ---------------- helpers ----------------
DEV float ex2f(float x) { float y; asm("ex2.approx.f32 %0, %1;" : "=f"(y) : "f"(x)); return y; }
DEV float lg2f(float x) { float y; asm("lg2.approx.f32 %0, %1;" : "=f"(y) : "f"(x)); return y; }

DEV uint32_t smem_u32(const void* p) {
    uint32_t a;
    asm("{ .reg .u64 t; cvta.to.shared.u64 t, %1; cvt.u32.u64 %0, t; }"
        : "=r"(a) : "l"(p));
    return a;
}
DEV void cp16(uint32_t saddr, const void* g) {
    asm volatile("cp.async.cg.shared.global [%0], [%1], 16;"
                 :: "r"(saddr), "l"(g) : "memory");
}
DEV void cp_commit() { asm volatile("cp.async.commit_group;" ::: "memory"); }
DEV void cp_wait0()  { asm volatile("cp.async.wait_group 0;" ::: "memory"); }

DEV void ldsm4(uint32_t* r, uint32_t addr) {
    asm volatile("ldmatrix.sync.aligned.m8n8.x4.shared.b16 {%0,%1,%2,%3}, [%4];"
                 : "=r"(r[0]), "=r"(r[1]), "=r"(r[2]), "=r"(r[3]) : "r"(addr));
}
DEV void mma16816(float* d, const uint32_t* a, const uint32_t* b) {
    asm volatile(
        "mma.sync.aligned.m16n8k16.row.col.f32.bf16.bf16.f32 "
        "{%0,%1,%2,%3}, {%4,%5,%6,%7}, {%8,%9}, {%0,%1,%2,%3};"
        : "+f"(d[0]), "+f"(d[1]), "+f"(d[2]), "+f"(d[3])
        : "r"(a[0]), "r"(a[1]), "r"(a[2]), "r"(a[3]), "r"(b[0]), "r"(b[1]));
}

// ---------------- kernel 1: normalize + prescale + bf16 (2 rows/warp for MLP) ----------------
__global__ void k_norm(const float* __restrict__ o1, const float* __restrict__ o2) {
    int w    = blockIdx.x * 8 + (threadIdx.x >> 5);   // 4096 warps
    int lane = threadIdx.x & 31;
    int r0 = w * 2, r1 = w * 2 + 1;
    const float* s0 = (r0 < BATCH) ? (o1 + (size_t)r0 * DIM) : (o2 + (size_t)(r0 - BATCH) * DIM);
    const float* s1 = (r1 < BATCH) ? (o1 + (size_t)r1 * DIM) : (o2 + (size_t)(r1 - BATCH) * DIM);
    float4 v0 = reinterpret_cast<const float4*>(s0)[lane];
    float4 v1 = reinterpret_cast<const float4*>(s1)[lane];
    float a = v0.x * v0.x + v0.y * v0.y + v0.z * v0.z + v0.w * v0.w;
    float b = v1.x * v1.x + v1.y * v1.y + v1.z * v1.z + v1.w * v1.w;
#pragma unroll
    for (int o = 16; o; o >>= 1) {
        a += __shfl_xor_sync(~0u, a, o);
        b += __shfl_xor_sync(~0u, b, o);
    }
    float c0 = rsqrtf(a) * PRESCALE;
    float c1 = rsqrtf(b) * PRESCALE;
    __nv_bfloat162 p0 = __floats2bfloat162_rn(v0.x * c0, v0.y * c0);
    __nv_bfloat162 p1 = __floats2bfloat162_rn(v0.z * c0, v0.w * c0);
    __nv_bfloat162 p2 = __floats2bfloat162_rn(v1.x * c1, v1.y * c1);
    __nv_bfloat162 p3 = __floats2bfloat162_rn(v1.z * c1, v1.w * c1);
    uint2 u0, u1;
    u0.x = *reinterpret_cast<uint32_t*>(&p0); u0.y = *reinterpret_cast<uint32_t*>(&p1);
    u1.x = *reinterpret_cast<uint32_t*>(&p2); u1.y = *reinterpret_cast<uint32_t*>(&p3);
    reinterpret_cast<uint2*>(&g_xn[(size_t)r0 * DIM])[lane] = u0;
    reinterpret_cast<uint2*>(&g_xn[(size_t)r1 * DIM])[lane] = u1;
}

// ---------------- kernel 2: tiled Gram (ldmatrix+mma) + boundless base-2 softmax sums ----------------
__global__ void __launch_bounds__(512, 1) k_sim() {
    extern __shared__ char smem[];
    const uint32_t sAu  = smem_u32(smem);
    const uint32_t sB0u = sAu + TILE_BYTES_SM;
    const uint32_t sB1u = sB0u + TILE_BYTES_SM;

    const int tid  = threadIdx.x;
    const int wid  = tid >> 5;
    const int lane = tid & 31;
    const int warp_m = wid & 3;       // 4 groups of 32 rows
    const int warp_n = wid >> 2;      // 4 groups of 32 cols
    const int cs  = blockIdx.x;       // column split 0/1
    const int rowBase = blockIdx.y * 128;
    const int colBase = cs * 4096;

    // ---- per-lane ldmatrix byte offsets (constant over ks via +ks*32) ----
    const int g  = lane >> 3;         // matrix index within x4
    const int lr = lane & 7;          // row within 8x8 matrix
    const int kg = (g >> 1) * 8;      // k offset 0/8
    uint32_t offA[2], offB[2];
#pragma unroll
    for (int i = 0; i < 2; i++) {
        int mrow = warp_m * 32 + i * 16 + (g & 1) * 8 + lr;
        offA[i] = (uint32_t)(mrow * SA + kg) * 2u;
    }
#pragma unroll
    for (int p = 0; p < 2; p++) {
        int nrow = warp_n * 32 + p * 16 + (g & 1) * 8 + lr;
        offB[p] = (uint32_t)(nrow * SA + kg) * 2u;
    }

    // ---- prologue: cp.async A tile + B tile 0 ----
#pragma unroll
    for (int i = 0; i < 4; i++) {
        int idx = tid + i * 512;
        int r   = idx >> 4;
        int kc  = (idx & 15) << 3;
        uint32_t so = (uint32_t)(r * SA + kc) * 2u;
        cp16(sAu  + so, &g_xn[(rowBase + r) * DIM + kc]);
        cp16(sB0u + so, &g_xn[(colBase + r) * DIM + kc]);
    }
    cp_commit();
    cp_wait0();
    __syncthreads();

    const int qr = lane >> 2;          // 0..7 (row within 8)
    const int qc = (lane & 3) * 2;     // 0,2,4,6 (col pair)
    const float NEG_INF = __int_as_float(0xff800000);

    float s[4] = {0.f, 0.f, 0.f, 0.f}; // per-thread row sums of exp2(logit)

    for (int t = 0; t < TILES; t++) {
        const uint32_t cur = (t & 1) ? sB1u : sB0u;
        const uint32_t nxt = (t & 1) ? sB0u : sB1u;

        // prefetch next B tile (async, no regs)
        if (t + 1 < TILES) {
#pragma unroll
            for (int i = 0; i < 4; i++) {
                int idx = tid + i * 512;
                int r   = idx >> 4;
                int kc  = (idx & 15) << 3;
                cp16(nxt + (uint32_t)(r * SA + kc) * 2u,
                     &g_xn[(colBase + (t + 1) * 128 + r) * DIM + kc]);
            }
            cp_commit();
        }

        // ---- 128x128 tile GEMM: each warp 32x32, acc[i][j][4] ----
        float acc[2][4][4];
#pragma unroll
        for (int i = 0; i < 2; i++)
#pragma unroll
            for (int j = 0; j < 4; j++)
#pragma unroll
                for (int c = 0; c < 4; c++) acc[i][j][c] = 0.f;

#pragma unroll
        for (int ks = 0; ks < 8; ks++) {
            const uint32_t kb = (uint32_t)ks * 32u;
            uint32_t a[2][4], b[4][2], bt[4];
            ldsm4(a[0], sAu + offA[0] + kb);
            ldsm4(a[1], sAu + offA[1] + kb);
            ldsm4(bt, cur + offB[0] + kb);
            b[0][0] = bt[0]; b[1][0] = bt[1]; b[0][1] = bt[2]; b[1][1] = bt[3];
            ldsm4(bt, cur + offB[1] + kb);
            b[2][0] = bt[0]; b[3][0] = bt[1]; b[2][1] = bt[2]; b[3][1] = bt[3];
#pragma unroll
            for (int i = 0; i < 2; i++)
#pragma unroll
                for (int j = 0; j < 4; j++)
                    mma16816(acc[i][j], a[i], b[j]);
        }

        // ---- epilogue: logits bounded (|v|<=14.43) -> plain exp2 accumulation ----
        const int  colT  = colBase + t * 128;
        const bool diagT = (colT == rowBase);
        const bool pairT = (colT == (rowBase ^ 4096));

        if (pairT | diagT) {
#pragma unroll
            for (int i = 0; i < 2; i++)
#pragma unroll
                for (int h = 0; h < 2; h++) {
                    const int rloc = warp_m * 32 + i * 16 + h * 8 + qr;
                    const int grow = rowBase + rloc;
                    if (pairT) {
                        const int tgt = ((grow ^ 4096) - colT) - warp_n * 32 - qc;
#pragma unroll
                        for (int j = 0; j < 4; j++) {
                            if (tgt == j * 8)     g_pair[grow] = acc[i][j][h * 2 + 0];
                            if (tgt == j * 8 + 1) g_pair[grow] = acc[i][j][h * 2 + 1];
                        }
                    }
                    if (diagT) {
                        const int tgt = rloc - warp_n * 32 - qc;
#pragma unroll
                        for (int j = 0; j < 4; j++) {
                            if (tgt == j * 8)     acc[i][j][h * 2 + 0] = NEG_INF;
                            if (tgt == j * 8 + 1) acc[i][j][h * 2 + 1] = NEG_INF;
                        }
                    }
                }
        }

#pragma unroll
        for (int i = 0; i < 2; i++)
#pragma unroll
            for (int h = 0; h < 2; h++) {
                float p0 = 0.f, p1 = 0.f;
#pragma unroll
                for (int j = 0; j < 4; j++) {
                    p0 += ex2f(acc[i][j][h * 2 + 0]);
                    p1 += ex2f(acc[i][j][h * 2 + 1]);
                }
                s[i * 2 + h] += p0 + p1;
            }

        if (t + 1 < TILES) cp_wait0();
        __syncthreads();
    }

    // ---- reduce: quad (same-row lanes), then across 4 warp_n groups via smem ----
#pragma unroll
    for (int ridx = 0; ridx < 4; ridx++) {
        s[ridx] += __shfl_xor_sync(~0u, s[ridx], 1);
        s[ridx] += __shfl_xor_sync(~0u, s[ridx], 2);
    }
    float* sc = reinterpret_cast<float*>(smem);     // [4][128]
    if ((lane & 3) == 0) {
#pragma unroll
        for (int ridx = 0; ridx < 4; ridx++) {
            const int i = ridx >> 1, h = ridx & 1;
            const int rloc = warp_m * 32 + i * 16 + h * 8 + qr;
            sc[warp_n * 128 + rloc] = s[ridx];
        }
    }
    __syncthreads();
    if (tid < 128) {
        float tot = (sc[tid] + sc[128 + tid]) + (sc[256 + tid] + sc[384 + tid]);
        g_s[cs][rowBase + tid] = tot;
    }
}

// ---------------- kernel 3: merge splits + reduce ----------------
__global__ void k_final(float* out) {
    __shared__ float red[32];
    const int tid = threadIdx.x;
    float acc = 0.f;
    for (int r = tid; r < NROW; r += 1024) {
        float sv = g_s[0][r] + g_s[1][r];
        acc += lg2f(sv) - g_pair[r];   // pos_r in base-2 units
    }
#pragma unroll
    for (int o = 16; o; o >>= 1) acc += __shfl_xor_sync(~0u, acc, o);
    if ((tid & 31) == 0) red[tid >> 5] = acc;
    __syncthreads();
    if (tid < 32) {
        float a = red[tid];
#pragma unroll
        for (int o = 16; o; o >>= 1) a += __shfl_xor_sync(~0u, a, o);
        if (tid == 0) out[0] = a * (0.6931471805599453f * 2048.0f); // ln2 * B/2
    }
}

// ---------------- launch ----------------
extern "C" void kernel_launch(void* const* d_in, const int* in_sizes, int n_in,
                              void* d_out, int out_size) {
    (void)in_sizes; (void)n_in; (void)out_size;
    const float* o1 = (const float*)d_in[0];
    const float* o2 = (const float*)d_in[1];

    k_norm<<<NROW / 16, 256>>>(o1, o2);

    static bool attr_set = false;
    if (!attr_set) {
        cudaFuncSetAttribute(k_sim, cudaFuncAttributeMaxDynamicSharedMemorySize, SMEM_BYTES);
        attr_set = true;
    }
    dim3 grid(2, 64);
    k_sim<<<grid, 512, SMEM_BYTES>>>();

    k_final<<<1, 1024>>>((float*)d_out);
}

// round 6
// speedup vs baseline: 1.3885x; 1.2388x over previous
#include <cuda_runtime.h>
#include <cuda_bf16.h>
#include <stdint.h>

#define DEV __device__ __forceinline__

namespace {
constexpr int BATCH = 4096;
constexpr int NROW  = 8192;   // 2B rows
constexpr int DIM   = 128;
constexpr int NBLK  = 64;     // 8192 / 128 row blocks
constexpr int NPAIR = NBLK * (NBLK + 1) / 2;   // 2080 upper-triangle block pairs
constexpr int SA    = 136;    // padded smem stride (bf16): conflict-free ldmatrix
constexpr unsigned TILE_B = 128u * SA * 2u;            // 34816 bytes per tile
constexpr unsigned SMEM_BYTES = 2u * TILE_B + 4096u;   // A,B + reduce arrays
// prescale: sqrt((1/T) * log2(e)) -> MMA output directly = base-2 logits
constexpr float PRESCALE = 3.79828310f;
}

// scratch (device globals: no allocations allowed)
__device__ __align__(256) __nv_bfloat16 g_xn[NROW * DIM];
__device__ float g_s[NROW];
__device__ float g_pair[NROW];

// ---------------- helpers ----------------
DEV float ex2f(float x) { float y; asm("ex2.approx.f32 %0, %1;" : "=f"(y) : "f"(x)); return y; }
DEV float lg2f(float x) { float y; asm("lg2.approx.f32 %0, %1;" : "=f"(y) : "f"(x)); return y; }

DEV uint32_t smem_u32(const void* p) {
    uint32_t a;
    asm("{ .reg .u64 t; cvta.to.shared.u64 t, %1; cvt.u32.u64 %0, t; }"
        : "=r"(a) : "l"(p));
    return a;
}
DEV void cp16(uint32_t saddr, const void* g) {
    asm volatile("cp.async.cg.shared.global [%0], [%1], 16;"
                 :: "r"(saddr), "l"(g) : "memory");
}
DEV void cp_commit() { asm volatile("cp.async.commit_group;" ::: "memory"); }
DEV void cp_wait0()  { asm volatile("cp.async.wait_group 0;" ::: "memory"); }

DEV void ldsm4(uint32_t* r, uint32_t addr) {
    asm volatile("ldmatrix.sync.aligned.m8n8.x4.shared.b16 {%0,%1,%2,%3}, [%4];"
                 : "=r"(r[0]), "=r"(r[1]), "=r"(r[2]), "=r"(r[3]) : "r"(addr));
}
DEV void mma16816(float* d, const uint32_t* a, const uint32_t* b) {
    asm volatile(
        "mma.sync.aligned.m16n8k16.row.col.f32.bf16.bf16.f32 "
        "{%0,%1,%2,%3}, {%4,%5,%6,%7}, {%8,%9}, {%0,%1,%2,%3};"
        : "+f"(d[0]), "+f"(d[1]), "+f"(d[2]), "+f"(d[3])
        : "r"(a[0]), "r"(a[1]), "r"(a[2]), "r"(a[3]), "r"(b[0]), "r"(b[1]));
}

// ---------------- kernel 1: normalize + prescale + bf16 (+ zero g_s) ----------------
__global__ void k_norm(const float* __restrict__ o1, const float* __restrict__ o2) {
    int gt = blockIdx.x * 256 + threadIdx.x;
    if (gt < NROW) g_s[gt] = 0.f;

    int w    = blockIdx.x * 8 + (threadIdx.x >> 5);   // 4096 warps
    int lane = threadIdx.x & 31;
    int r0 = w * 2, r1 = w * 2 + 1;
    const float* s0 = (r0 < BATCH) ? (o1 + (size_t)r0 * DIM) : (o2 + (size_t)(r0 - BATCH) * DIM);
    const float* s1 = (r1 < BATCH) ? (o1 + (size_t)r1 * DIM) : (o2 + (size_t)(r1 - BATCH) * DIM);
    float4 v0 = reinterpret_cast<const float4*>(s0)[lane];
    float4 v1 = reinterpret_cast<const float4*>(s1)[lane];
    float a = v0.x * v0.x + v0.y * v0.y + v0.z * v0.z + v0.w * v0.w;
    float b = v1.x * v1.x + v1.y * v1.y + v1.z * v1.z + v1.w * v1.w;
#pragma unroll
    for (int o = 16; o; o >>= 1) {
        a += __shfl_xor_sync(~0u, a, o);
        b += __shfl_xor_sync(~0u, b, o);
    }
    float c0 = rsqrtf(a) * PRESCALE;
    float c1 = rsqrtf(b) * PRESCALE;
    __nv_bfloat162 p0 = __floats2bfloat162_rn(v0.x * c0, v0.y * c0);
    __nv_bfloat162 p1 = __floats2bfloat162_rn(v0.z * c0, v0.w * c0);
    __nv_bfloat162 p2 = __floats2bfloat162_rn(v1.x * c1, v1.y * c1);
    __nv_bfloat162 p3 = __floats2bfloat162_rn(v1.z * c1, v1.w * c1);
    uint2 u0, u1;
    u0.x = *reinterpret_cast<uint32_t*>(&p0); u0.y = *reinterpret_cast<uint32_t*>(&p1);
    u1.x = *reinterpret_cast<uint32_t*>(&p2); u1.y = *reinterpret_cast<uint32_t*>(&p3);
    reinterpret_cast<uint2*>(&g_xn[(size_t)r0 * DIM])[lane] = u0;
    reinterpret_cast<uint2*>(&g_xn[(size_t)r1 * DIM])[lane] = u1;
}

// ---------------- kernel 2: one symmetric block-pair per CTA ----------------
__global__ void __launch_bounds__(512, 1) k_sim() {
    extern __shared__ char smem[];
    const uint32_t sAu = smem_u32(smem);
    const uint32_t sBu = sAu + TILE_B;
    float* smRow = reinterpret_cast<float*>(smem + 2 * TILE_B);   // [4][128]
    float* smCol = smRow + 512;                                   // [4][128]

    const int tid  = threadIdx.x;
    const int wid  = tid >> 5;
    const int lane = tid & 31;
    const int warp_m = wid & 3;       // 4 groups of 32 rows
    const int warp_n = wid >> 2;      // 4 groups of 32 cols

    // ---- decode pair (I, J) from blockIdx, J >= I (bounded loop) ----
    int I = 0, rem = blockIdx.x;
#pragma unroll 1
    for (; I < NBLK - 1 && rem >= NBLK - I; I++) rem -= NBLK - I;
    const int J = I + rem;

    // ---- load both tiles via cp.async ----
#pragma unroll
    for (int i = 0; i < 4; i++) {
        int idx = tid + i * 512;
        int r   = idx >> 4;
        int kc  = (idx & 15) << 3;
        uint32_t so = (uint32_t)(r * SA + kc) * 2u;
        cp16(sAu + so, &g_xn[(I * 128 + r) * DIM + kc]);
        cp16(sBu + so, &g_xn[(J * 128 + r) * DIM + kc]);
    }
    cp_commit();

    // ldmatrix per-lane offsets
    const int g  = lane >> 3;
    const int lr = lane & 7;
    const int kg = (g >> 1) * 8;
    uint32_t offA[2], offB[2];
#pragma unroll
    for (int i = 0; i < 2; i++)
        offA[i] = sAu + (uint32_t)((warp_m * 32 + i * 16 + (g & 1) * 8 + lr) * SA + kg) * 2u;
#pragma unroll
    for (int p = 0; p < 2; p++)
        offB[p] = sBu + (uint32_t)((warp_n * 32 + p * 16 + (g & 1) * 8 + lr) * SA + kg) * 2u;

    cp_wait0();
    __syncthreads();

    const int qr = lane >> 2;
    const int qc = (lane & 3) * 2;
    const float NEG_INF = __int_as_float(0xff800000);

    // ---- 128x128 tile GEMM: each warp 32x32 ----
    float acc[2][4][4];
#pragma unroll
    for (int i = 0; i < 2; i++)
#pragma unroll
        for (int j = 0; j < 4; j++)
#pragma unroll
            for (int c = 0; c < 4; c++) acc[i][j][c] = 0.f;

#pragma unroll
    for (int ks = 0; ks < 8; ks++) {
        const uint32_t kb = (uint32_t)ks * 32u;
        uint32_t a[2][4], b[4][2], bt[4];
        ldsm4(a[0], offA[0] + kb);
        ldsm4(a[1], offA[1] + kb);
        ldsm4(bt, offB[0] + kb);
        b[0][0] = bt[0]; b[1][0] = bt[1]; b[0][1] = bt[2]; b[1][1] = bt[3];
        ldsm4(bt, offB[1] + kb);
        b[2][0] = bt[0]; b[3][0] = bt[1]; b[2][1] = bt[2]; b[3][1] = bt[3];
#pragma unroll
        for (int i = 0; i < 2; i++)
#pragma unroll
            for (int j = 0; j < 4; j++)
                mma16816(acc[i][j], a[i], b[j]);
    }

    // ---- special tiles: diagonal mask / positive-pair capture ----
    if (J == I) {
#pragma unroll
        for (int i = 0; i < 2; i++)
#pragma unroll
            for (int h = 0; h < 2; h++) {
                const int rloc = warp_m * 32 + i * 16 + h * 8 + qr;
                const int tgt  = rloc - warp_n * 32 - qc;
#pragma unroll
                for (int j = 0; j < 4; j++) {
                    if (tgt == j * 8)     acc[i][j][h * 2 + 0] = NEG_INF;
                    if (tgt == j * 8 + 1) acc[i][j][h * 2 + 1] = NEG_INF;
                }
            }
    } else if (J == I + 32) {
        // local diagonal holds the positive pairs: row I*128+r <-> col J*128+r
#pragma unroll
        for (int i = 0; i < 2; i++)
#pragma unroll
            for (int h = 0; h < 2; h++) {
                const int rloc = warp_m * 32 + i * 16 + h * 8 + qr;
                const int tgt  = rloc - warp_n * 32 - qc;
#pragma unroll
                for (int j = 0; j < 4; j++) {
                    if (tgt == j * 8) {
                        float v = acc[i][j][h * 2 + 0];
                        g_pair[I * 128 + rloc] = v;
                        g_pair[I * 128 + rloc + 4096] = v;
                    }
                    if (tgt == j * 8 + 1) {
                        float v = acc[i][j][h * 2 + 1];
                        g_pair[I * 128 + rloc] = v;
                        g_pair[I * 128 + rloc + 4096] = v;
                    }
                }
            }
    }

    // ---- epilogue: exp2 once; accumulate row AND col partials ----
    float rowp[4] = {0.f, 0.f, 0.f, 0.f};
    float colp[4][2];
#pragma unroll
    for (int j = 0; j < 4; j++) { colp[j][0] = 0.f; colp[j][1] = 0.f; }

#pragma unroll
    for (int i = 0; i < 2; i++)
#pragma unroll
        for (int h = 0; h < 2; h++) {
#pragma unroll
            for (int j = 0; j < 4; j++) {
                float e0 = ex2f(acc[i][j][h * 2 + 0]);
                float e1 = ex2f(acc[i][j][h * 2 + 1]);
                rowp[i * 2 + h] += e0 + e1;
                colp[j][0] += e0;
                colp[j][1] += e1;
            }
        }

    // row reduce within quad (lanes sharing a row)
#pragma unroll
    for (int r = 0; r < 4; r++) {
        rowp[r] += __shfl_xor_sync(~0u, rowp[r], 1);
        rowp[r] += __shfl_xor_sync(~0u, rowp[r], 2);
    }
    // col reduce across qr lanes (lanes sharing a col)
#pragma unroll
    for (int j = 0; j < 4; j++)
#pragma unroll
        for (int c = 0; c < 2; c++) {
            colp[j][c] += __shfl_xor_sync(~0u, colp[j][c], 4);
            colp[j][c] += __shfl_xor_sync(~0u, colp[j][c], 8);
            colp[j][c] += __shfl_xor_sync(~0u, colp[j][c], 16);
        }

    if ((lane & 3) == 0) {
#pragma unroll
        for (int r = 0; r < 4; r++) {
            const int i = r >> 1, h = r & 1;
            smRow[warp_n * 128 + warp_m * 32 + i * 16 + h * 8 + qr] = rowp[r];
        }
    }
    if (qr == 0) {
#pragma unroll
        for (int j = 0; j < 4; j++)
#pragma unroll
            for (int c = 0; c < 2; c++)
                smCol[warp_m * 128 + warp_n * 32 + j * 8 + qc + c] = colp[j][c];
    }
    __syncthreads();
    if (tid < 128) {
        float rs = (smRow[tid] + smRow[128 + tid]) + (smRow[256 + tid] + smRow[384 + tid]);
        atomicAdd(&g_s[I * 128 + tid], rs);
        if (J != I) {
            float cssum = (smCol[tid] + smCol[128 + tid]) + (smCol[256 + tid] + smCol[384 + tid]);
            atomicAdd(&g_s[J * 128 + tid], cssum);
        }
    }
}

// ---------------- kernel 3: final reduce ----------------
__global__ void k_final(float* out) {
    __shared__ float red[32];
    const int tid = threadIdx.x;
    float acc = 0.f;
    for (int r = tid; r < NROW; r += 1024)
        acc += lg2f(g_s[r]) - g_pair[r];   // pos_r in base-2 units
#pragma unroll
    for (int o = 16; o; o >>= 1) acc += __shfl_xor_sync(~0u, acc, o);
    if ((tid & 31) == 0) red[tid >> 5] = acc;
    __syncthreads();
    if (tid < 32) {
        float a = red[tid];
#pragma unroll
        for (int o = 16; o; o >>= 1) a += __shfl_xor_sync(~0u, a, o);
        if (tid == 0) out[0] = a * (0.6931471805599453f * 2048.0f); // ln2 * B/2
    }
}

// ---------------- launch ----------------
extern "C" void kernel_launch(void* const* d_in, const int* in_sizes, int n_in,
                              void* d_out, int out_size) {
    (void)in_sizes; (void)n_in; (void)out_size;
    const float* o1 = (const float*)d_in[0];
    const float* o2 = (const float*)d_in[1];

    k_norm<<<NROW / 16, 256>>>(o1, o2);

    static bool attr_set = false;
    if (!attr_set) {
        cudaFuncSetAttribute(k_sim, cudaFuncAttributeMaxDynamicSharedMemorySize, SMEM_BYTES);
        attr_set = true;
    }
    k_sim<<<NPAIR, 512, SMEM_BYTES>>>();

    k_final<<<1, 1024>>>((float*)d_out);
}

// round 7
// speedup vs baseline: 1.9352x; 1.3937x over previous
#include <cuda_runtime.h>
#include <cuda_bf16.h>
#include <stdint.h>

#define DEV __device__ __forceinline__

namespace {
constexpr int BATCH = 4096;
constexpr int NROW  = 8192;   // 2B rows
constexpr int DIM   = 128;
constexpr int NBLK  = 64;     // 8192 / 128 row blocks
constexpr int NPAIR = NBLK * (NBLK + 1) / 2;   // 2080 upper-triangle block pairs
constexpr int SA    = 136;    // padded smem stride (bf16): conflict-free ldmatrix
constexpr unsigned TILE_B = 128u * SA * 2u;            // 34816 bytes per tile
constexpr unsigned SMEM_BYTES = 2u * TILE_B + 4096u;   // A,B + reduce arrays
// prescale: sqrt((1/T) * log2(e)) -> MMA output directly = base-2 logits
constexpr float PRESCALE = 3.79828310f;
}

// scratch (device globals: no allocations allowed)
__device__ __align__(256) __nv_bfloat16 g_xn[NROW * DIM];
__device__ float g_s[NROW];
__device__ float g_pair[NROW];

// ---------------- helpers ----------------
DEV float ex2f(float x) { float y; asm("ex2.approx.f32 %0, %1;" : "=f"(y) : "f"(x)); return y; }
DEV float lg2f(float x) { float y; asm("lg2.approx.f32 %0, %1;" : "=f"(y) : "f"(x)); return y; }

DEV uint32_t smem_u32(const void* p) {
    uint32_t a;
    asm("{ .reg .u64 t; cvta.to.shared.u64 t, %1; cvt.u32.u64 %0, t; }"
        : "=r"(a) : "l"(p));
    return a;
}
DEV void cp16(uint32_t saddr, const void* g) {
    asm volatile("cp.async.cg.shared.global [%0], [%1], 16;"
                 :: "r"(saddr), "l"(g) : "memory");
}
DEV void cp_commit() { asm volatile("cp.async.commit_group;" ::: "memory"); }
DEV void cp_wait0()  { asm volatile("cp.async.wait_group 0;" ::: "memory"); }

DEV void ldsm4(uint32_t* r, uint32_t addr) {
    asm volatile("ldmatrix.sync.aligned.m8n8.x4.shared.b16 {%0,%1,%2,%3}, [%4];"
                 : "=r"(r[0]), "=r"(r[1]), "=r"(r[2]), "=r"(r[3]) : "r"(addr));
}
DEV void mma16816(float* d, const uint32_t* a, const uint32_t* b) {
    asm volatile(
        "mma.sync.aligned.m16n8k16.row.col.f32.bf16.bf16.f32 "
        "{%0,%1,%2,%3}, {%4,%5,%6,%7}, {%8,%9}, {%0,%1,%2,%3};"
        : "+f"(d[0]), "+f"(d[1]), "+f"(d[2]), "+f"(d[3])
        : "r"(a[0]), "r"(a[1]), "r"(a[2]), "r"(a[3]), "r"(b[0]), "r"(b[1]));
}

// ---------------- kernel 1: normalize + prescale + bf16 (+ zero g_s) ----------------
// 4 rows per warp, loads front-batched for MLP=4
__global__ void k_norm(const float* __restrict__ o1, const float* __restrict__ o2) {
    int gt = blockIdx.x * 256 + threadIdx.x;
    if (gt < NROW) g_s[gt] = 0.f;

    int w    = blockIdx.x * 8 + (threadIdx.x >> 5);   // 2048 warps
    int lane = threadIdx.x & 31;
    float4 v[4];
    int rows[4];
#pragma unroll
    for (int i = 0; i < 4; i++) {
        int r = w * 4 + i;
        rows[i] = r;
        const float* s = (r < BATCH) ? (o1 + (size_t)r * DIM)
                                     : (o2 + (size_t)(r - BATCH) * DIM);
        v[i] = reinterpret_cast<const float4*>(s)[lane];
    }
    float ss[4];
#pragma unroll
    for (int i = 0; i < 4; i++)
        ss[i] = v[i].x * v[i].x + v[i].y * v[i].y + v[i].z * v[i].z + v[i].w * v[i].w;
#pragma unroll
    for (int o = 16; o; o >>= 1) {
#pragma unroll
        for (int i = 0; i < 4; i++) ss[i] += __shfl_xor_sync(~0u, ss[i], o);
    }
#pragma unroll
    for (int i = 0; i < 4; i++) {
        float sc = rsqrtf(ss[i]) * PRESCALE;
        __nv_bfloat162 p0 = __floats2bfloat162_rn(v[i].x * sc, v[i].y * sc);
        __nv_bfloat162 p1 = __floats2bfloat162_rn(v[i].z * sc, v[i].w * sc);
        uint2 u;
        u.x = *reinterpret_cast<uint32_t*>(&p0);
        u.y = *reinterpret_cast<uint32_t*>(&p1);
        reinterpret_cast<uint2*>(&g_xn[(size_t)rows[i] * DIM])[lane] = u;
    }
}

// ---------------- kernel 2: one symmetric block-pair per CTA (256 thr, 2 CTA/SM) ----------------
__global__ void __launch_bounds__(256, 2) k_sim() {
    extern __shared__ char smem[];
    const uint32_t sAu = smem_u32(smem);
    const uint32_t sBu = sAu + TILE_B;
    float* smRow = reinterpret_cast<float*>(smem + 2 * TILE_B);   // [2][128]
    float* smCol = smRow + 256;                                   // [4][128]

    const int tid  = threadIdx.x;
    const int wid  = tid >> 5;
    const int lane = tid & 31;
    const int warp_m = wid & 3;       // 4 groups of 32 rows
    const int warp_n = wid >> 2;      // 2 groups of 64 cols

    // ---- decode pair (I, J) from blockIdx, J >= I (bounded loop) ----
    int I = 0, rem = blockIdx.x;
#pragma unroll 1
    for (; I < NBLK - 1 && rem >= NBLK - I; I++) rem -= NBLK - I;
    const int J = I + rem;

    // ---- load both tiles via cp.async (16 chunks / thread) ----
#pragma unroll
    for (int i = 0; i < 8; i++) {
        int idx = tid + i * 256;
        int r   = idx >> 4;
        int kc  = (idx & 15) << 3;
        uint32_t so = (uint32_t)(r * SA + kc) * 2u;
        cp16(sAu + so, &g_xn[(I * 128 + r) * DIM + kc]);
        cp16(sBu + so, &g_xn[(J * 128 + r) * DIM + kc]);
    }
    cp_commit();

    // ldmatrix per-lane offsets
    const int g  = lane >> 3;
    const int lr = lane & 7;
    const int kg = (g >> 1) * 8;
    uint32_t offA[2], offB[4];
#pragma unroll
    for (int i = 0; i < 2; i++)
        offA[i] = sAu + (uint32_t)((warp_m * 32 + i * 16 + (g & 1) * 8 + lr) * SA + kg) * 2u;
#pragma unroll
    for (int p = 0; p < 4; p++)
        offB[p] = sBu + (uint32_t)((warp_n * 64 + p * 16 + (g & 1) * 8 + lr) * SA + kg) * 2u;

    cp_wait0();
    __syncthreads();

    const int qr = lane >> 2;
    const int qc = (lane & 3) * 2;
    const float NEG_INF = __int_as_float(0xff800000);

    // ---- 128x128 tile GEMM: each warp 32 rows x 64 cols ----
    float acc[2][8][4];
#pragma unroll
    for (int i = 0; i < 2; i++)
#pragma unroll
        for (int j = 0; j < 8; j++)
#pragma unroll
            for (int c = 0; c < 4; c++) acc[i][j][c] = 0.f;

#pragma unroll
    for (int ks = 0; ks < 8; ks++) {
        const uint32_t kb = (uint32_t)ks * 32u;
        uint32_t a[2][4], b[8][2], bt[4];
        ldsm4(a[0], offA[0] + kb);
        ldsm4(a[1], offA[1] + kb);
#pragma unroll
        for (int p = 0; p < 4; p++) {
            ldsm4(bt, offB[p] + kb);
            b[p * 2 + 0][0] = bt[0];
            b[p * 2 + 1][0] = bt[1];
            b[p * 2 + 0][1] = bt[2];
            b[p * 2 + 1][1] = bt[3];
        }
#pragma unroll
        for (int i = 0; i < 2; i++)
#pragma unroll
            for (int j = 0; j < 8; j++)
                mma16816(acc[i][j], a[i], b[j]);
    }

    // ---- special tiles: diagonal mask / positive-pair capture ----
    if (J == I) {
#pragma unroll
        for (int i = 0; i < 2; i++)
#pragma unroll
            for (int h = 0; h < 2; h++) {
                const int rloc = warp_m * 32 + i * 16 + h * 8 + qr;
                const int tgt  = rloc - warp_n * 64 - qc;
#pragma unroll
                for (int j = 0; j < 8; j++) {
                    if (tgt == j * 8)     acc[i][j][h * 2 + 0] = NEG_INF;
                    if (tgt == j * 8 + 1) acc[i][j][h * 2 + 1] = NEG_INF;
                }
            }
    } else if (J == I + 32) {
        // local diagonal holds the positive pairs: row I*128+r <-> col J*128+r
#pragma unroll
        for (int i = 0; i < 2; i++)
#pragma unroll
            for (int h = 0; h < 2; h++) {
                const int rloc = warp_m * 32 + i * 16 + h * 8 + qr;
                const int tgt  = rloc - warp_n * 64 - qc;
#pragma unroll
                for (int j = 0; j < 8; j++) {
                    if (tgt == j * 8) {
                        float val = acc[i][j][h * 2 + 0];
                        g_pair[I * 128 + rloc] = val;
                        g_pair[I * 128 + rloc + 4096] = val;
                    }
                    if (tgt == j * 8 + 1) {
                        float val = acc[i][j][h * 2 + 1];
                        g_pair[I * 128 + rloc] = val;
                        g_pair[I * 128 + rloc + 4096] = val;
                    }
                }
            }
    }

    // ---- epilogue: exp2 once; accumulate row AND col partials ----
    float rowp[4] = {0.f, 0.f, 0.f, 0.f};
    float colp[8][2];
#pragma unroll
    for (int j = 0; j < 8; j++) { colp[j][0] = 0.f; colp[j][1] = 0.f; }

#pragma unroll
    for (int i = 0; i < 2; i++)
#pragma unroll
        for (int h = 0; h < 2; h++) {
#pragma unroll
            for (int j = 0; j < 8; j++) {
                float e0 = ex2f(acc[i][j][h * 2 + 0]);
                float e1 = ex2f(acc[i][j][h * 2 + 1]);
                rowp[i * 2 + h] += e0 + e1;
                colp[j][0] += e0;
                colp[j][1] += e1;
            }
        }

    // row reduce within quad (lanes sharing a row)
#pragma unroll
    for (int r = 0; r < 4; r++) {
        rowp[r] += __shfl_xor_sync(~0u, rowp[r], 1);
        rowp[r] += __shfl_xor_sync(~0u, rowp[r], 2);
    }
    // col reduce across qr lanes (lanes sharing a col)
#pragma unroll
    for (int j = 0; j < 8; j++)
#pragma unroll
        for (int c = 0; c < 2; c++) {
            colp[j][c] += __shfl_xor_sync(~0u, colp[j][c], 4);
            colp[j][c] += __shfl_xor_sync(~0u, colp[j][c], 8);
            colp[j][c] += __shfl_xor_sync(~0u, colp[j][c], 16);
        }

    if ((lane & 3) == 0) {
#pragma unroll
        for (int r = 0; r < 4; r++) {
            const int i = r >> 1, h = r & 1;
            smRow[warp_n * 128 + warp_m * 32 + i * 16 + h * 8 + qr] = rowp[r];
        }
    }
    if (qr == 0) {
#pragma unroll
        for (int j = 0; j < 8; j++)
#pragma unroll
            for (int c = 0; c < 2; c++)
                smCol[warp_m * 128 + warp_n * 64 + j * 8 + qc + c] = colp[j][c];
    }
    __syncthreads();
    if (tid < 128) {
        float rs = smRow[tid] + smRow[128 + tid];
        atomicAdd(&g_s[I * 128 + tid], rs);
        if (J != I) {
            float cssum = (smCol[tid] + smCol[128 + tid]) + (smCol[256 + tid] + smCol[384 + tid]);
            atomicAdd(&g_s[J * 128 + tid], cssum);
        }
    }
}

// ---------------- kernel 3: final reduce ----------------
__global__ void k_final(float* out) {
    __shared__ float red[32];
    const int tid = threadIdx.x;
    float acc = 0.f;
    for (int r = tid; r < NROW; r += 1024)
        acc += lg2f(g_s[r]) - g_pair[r];   // pos_r in base-2 units
#pragma unroll
    for (int o = 16; o; o >>= 1) acc += __shfl_xor_sync(~0u, acc, o);
    if ((tid & 31) == 0) red[tid >> 5] = acc;
    __syncthreads();
    if (tid < 32) {
        float a = red[tid];
#pragma unroll
        for (int o = 16; o; o >>= 1) a += __shfl_xor_sync(~0u, a, o);
        if (tid == 0) out[0] = a * (0.6931471805599453f * 2048.0f); // ln2 * B/2
    }
}

// ---------------- launch ----------------
extern "C" void kernel_launch(void* const* d_in, const int* in_sizes, int n_in,
                              void* d_out, int out_size) {
    (void)in_sizes; (void)n_in; (void)out_size;
    const float* o1 = (const float*)d_in[0];
    const float* o2 = (const float*)d_in[1];

    k_norm<<<NROW / 32, 256>>>(o1, o2);

    static bool attr_set = false;
    if (!attr_set) {
        cudaFuncSetAttribute(k_sim, cudaFuncAttributeMaxDynamicSharedMemorySize, SMEM_BYTES);
        attr_set = true;
    }
    k_sim<<<NPAIR, 256, SMEM_BYTES>>>();

    k_final<<<1, 1024>>>((float*)d_out);
}

// round 8
// speedup vs baseline: 2.0118x; 1.0396x over previous
#include <cuda_runtime.h>
#include <cuda_bf16.h>
#include <stdint.h>

#define DEV __device__ __forceinline__

namespace {
constexpr int BATCH = 4096;
constexpr int NROW  = 8192;   // 2B rows
constexpr int DIM   = 128;
constexpr int NBLK  = 64;     // 8192 / 128 row blocks
constexpr int NPAIR = NBLK * (NBLK + 1) / 2;   // 2080 (even)
constexpr int SA    = 136;    // padded smem stride (bf16): conflict-free ldmatrix
constexpr unsigned TILE_B = 128u * SA * 2u;            // 34816 bytes per tile
constexpr unsigned SMEM_BYTES = 3u * TILE_B + 4096u;   // A,B1,B2 + reduce arrays
// prescale: sqrt((1/T) * log2(e)) -> MMA output directly = base-2 logits
constexpr float PRESCALE = 3.79828310f;
}

// scratch (device globals: no allocations allowed)
__device__ __align__(256) __nv_bfloat16 g_xn[NROW * DIM];
__device__ float g_s[NROW];
__device__ float g_pair[NROW];

// ---------------- helpers ----------------
DEV float ex2f(float x) { float y; asm("ex2.approx.f32 %0, %1;" : "=f"(y) : "f"(x)); return y; }
DEV float lg2f(float x) { float y; asm("lg2.approx.f32 %0, %1;" : "=f"(y) : "f"(x)); return y; }

DEV uint32_t smem_u32(const void* p) {
    uint32_t a;
    asm("{ .reg .u64 t; cvta.to.shared.u64 t, %1; cvt.u32.u64 %0, t; }"
        : "=r"(a) : "l"(p));
    return a;
}
DEV void cp16(uint32_t saddr, const void* g) {
    asm volatile("cp.async.cg.shared.global [%0], [%1], 16;"
                 :: "r"(saddr), "l"(g) : "memory");
}
DEV void cp_commit() { asm volatile("cp.async.commit_group;" ::: "memory"); }
DEV void cp_wait0()  { asm volatile("cp.async.wait_group 0;" ::: "memory"); }

DEV void ldsm4(uint32_t* r, uint32_t addr) {
    asm volatile("ldmatrix.sync.aligned.m8n8.x4.shared.b16 {%0,%1,%2,%3}, [%4];"
                 : "=r"(r[0]), "=r"(r[1]), "=r"(r[2]), "=r"(r[3]) : "r"(addr));
}
DEV void mma16816(float* d, const uint32_t* a, const uint32_t* b) {
    asm volatile(
        "mma.sync.aligned.m16n8k16.row.col.f32.bf16.bf16.f32 "
        "{%0,%1,%2,%3}, {%4,%5,%6,%7}, {%8,%9}, {%0,%1,%2,%3};"
        : "+f"(d[0]), "+f"(d[1]), "+f"(d[2]), "+f"(d[3])
        : "r"(a[0]), "r"(a[1]), "r"(a[2]), "r"(a[3]), "r"(b[0]), "r"(b[1]));
}

// ---------------- one 128x128 block-pair: GEMM + masked exp2 epilogue ----------------
DEV void do_pair(uint32_t aB, uint32_t bB, int I, int J,
                 int tid, int wid, int lane, float* smRow, float* smCol) {
    const int warp_m = wid & 3;       // 4 groups of 32 rows
    const int warp_n = wid >> 2;      // 2 groups of 64 cols
    const int g  = lane >> 3;
    const int lr = lane & 7;
    const int kg = (g >> 1) * 8;
    uint32_t offA[2], offB[4];
#pragma unroll
    for (int i = 0; i < 2; i++)
        offA[i] = aB + (uint32_t)((warp_m * 32 + i * 16 + (g & 1) * 8 + lr) * SA + kg) * 2u;
#pragma unroll
    for (int p = 0; p < 4; p++)
        offB[p] = bB + (uint32_t)((warp_n * 64 + p * 16 + (g & 1) * 8 + lr) * SA + kg) * 2u;

    const int qr = lane >> 2;
    const int qc = (lane & 3) * 2;
    const float NEG_INF = __int_as_float(0xff800000);

    float acc[2][8][4];
#pragma unroll
    for (int i = 0; i < 2; i++)
#pragma unroll
        for (int j = 0; j < 8; j++)
#pragma unroll
            for (int c = 0; c < 4; c++) acc[i][j][c] = 0.f;

#pragma unroll
    for (int ks = 0; ks < 8; ks++) {
        const uint32_t kb = (uint32_t)ks * 32u;
        uint32_t a[2][4], b[8][2], bt[4];
        ldsm4(a[0], offA[0] + kb);
        ldsm4(a[1], offA[1] + kb);
#pragma unroll
        for (int p = 0; p < 4; p++) {
            ldsm4(bt, offB[p] + kb);
            b[p * 2 + 0][0] = bt[0];
            b[p * 2 + 1][0] = bt[1];
            b[p * 2 + 0][1] = bt[2];
            b[p * 2 + 1][1] = bt[3];
        }
#pragma unroll
        for (int i = 0; i < 2; i++)
#pragma unroll
            for (int j = 0; j < 8; j++)
                mma16816(acc[i][j], a[i], b[j]);
    }

    // special tiles: diagonal mask / positive-pair capture
    if (J == I) {
#pragma unroll
        for (int i = 0; i < 2; i++)
#pragma unroll
            for (int h = 0; h < 2; h++) {
                const int rloc = warp_m * 32 + i * 16 + h * 8 + qr;
                const int tgt  = rloc - warp_n * 64 - qc;
#pragma unroll
                for (int j = 0; j < 8; j++) {
                    if (tgt == j * 8)     acc[i][j][h * 2 + 0] = NEG_INF;
                    if (tgt == j * 8 + 1) acc[i][j][h * 2 + 1] = NEG_INF;
                }
            }
    } else if (J == I + 32) {
        // local diagonal holds the positive pairs: row I*128+r <-> col J*128+r
#pragma unroll
        for (int i = 0; i < 2; i++)
#pragma unroll
            for (int h = 0; h < 2; h++) {
                const int rloc = warp_m * 32 + i * 16 + h * 8 + qr;
                const int tgt  = rloc - warp_n * 64 - qc;
#pragma unroll
                for (int j = 0; j < 8; j++) {
                    if (tgt == j * 8) {
                        float val = acc[i][j][h * 2 + 0];
                        g_pair[I * 128 + rloc] = val;
                        g_pair[I * 128 + rloc + 4096] = val;
                    }
                    if (tgt == j * 8 + 1) {
                        float val = acc[i][j][h * 2 + 1];
                        g_pair[I * 128 + rloc] = val;
                        g_pair[I * 128 + rloc + 4096] = val;
                    }
                }
            }
    }

    // epilogue: exp2 once; accumulate row AND col partials
    float rowp[4] = {0.f, 0.f, 0.f, 0.f};
    float colp[8][2];
#pragma unroll
    for (int j = 0; j < 8; j++) { colp[j][0] = 0.f; colp[j][1] = 0.f; }

#pragma unroll
    for (int i = 0; i < 2; i++)
#pragma unroll
        for (int h = 0; h < 2; h++) {
#pragma unroll
            for (int j = 0; j < 8; j++) {
                float e0 = ex2f(acc[i][j][h * 2 + 0]);
                float e1 = ex2f(acc[i][j][h * 2 + 1]);
                rowp[i * 2 + h] += e0 + e1;
                colp[j][0] += e0;
                colp[j][1] += e1;
            }
        }

    // row reduce within quad (lanes sharing a row)
#pragma unroll
    for (int r = 0; r < 4; r++) {
        rowp[r] += __shfl_xor_sync(~0u, rowp[r], 1);
        rowp[r] += __shfl_xor_sync(~0u, rowp[r], 2);
    }
    // col reduce across qr lanes (lanes sharing a col)
#pragma unroll
    for (int j = 0; j < 8; j++)
#pragma unroll
        for (int c = 0; c < 2; c++) {
            colp[j][c] += __shfl_xor_sync(~0u, colp[j][c], 4);
            colp[j][c] += __shfl_xor_sync(~0u, colp[j][c], 8);
            colp[j][c] += __shfl_xor_sync(~0u, colp[j][c], 16);
        }

    if ((lane & 3) == 0) {
#pragma unroll
        for (int r = 0; r < 4; r++) {
            const int i = r >> 1, h = r & 1;
            smRow[warp_n * 128 + warp_m * 32 + i * 16 + h * 8 + qr] = rowp[r];
        }
    }
    if (qr == 0) {
#pragma unroll
        for (int j = 0; j < 8; j++)
#pragma unroll
            for (int c = 0; c < 2; c++)
                smCol[warp_m * 128 + warp_n * 64 + j * 8 + qc + c] = colp[j][c];
    }
    __syncthreads();
    if (tid < 128) {
        float rs = smRow[tid] + smRow[128 + tid];
        atomicAdd(&g_s[I * 128 + tid], rs);
        if (J != I) {
            float cssum = (smCol[tid] + smCol[128 + tid]) + (smCol[256 + tid] + smCol[384 + tid]);
            atomicAdd(&g_s[J * 128 + tid], cssum);
        }
    }
    __syncthreads();   // protect smRow/smCol for the next pair
}

// ---------------- kernel 1: normalize + prescale + bf16 (+ zero g_s) ----------------
// 1 row per warp, 1024 CTAs: maximize chip-wide MLP (kernel is latency-bound)
__global__ void k_norm(const float* __restrict__ o1, const float* __restrict__ o2) {
    int gt = blockIdx.x * 256 + threadIdx.x;
    if (gt < NROW) g_s[gt] = 0.f;

    int row  = blockIdx.x * 8 + (threadIdx.x >> 5);   // 8192 warps, 1 row each
    int lane = threadIdx.x & 31;
    const float* src = (row < BATCH) ? (o1 + (size_t)row * DIM)
                                     : (o2 + (size_t)(row - BATCH) * DIM);
    float4 v = reinterpret_cast<const float4*>(src)[lane];
    float ss = v.x * v.x + v.y * v.y + v.z * v.z + v.w * v.w;
#pragma unroll
    for (int o = 16; o; o >>= 1) ss += __shfl_xor_sync(~0u, ss, o);
    float sc = rsqrtf(ss) * PRESCALE;
    __nv_bfloat162 p0 = __floats2bfloat162_rn(v.x * sc, v.y * sc);
    __nv_bfloat162 p1 = __floats2bfloat162_rn(v.z * sc, v.w * sc);
    uint2 u;
    u.x = *reinterpret_cast<uint32_t*>(&p0);
    u.y = *reinterpret_cast<uint32_t*>(&p1);
    reinterpret_cast<uint2*>(&g_xn[(size_t)row * DIM])[lane] = u;
}

// ---------------- kernel 2: two consecutive block-pairs per CTA ----------------
__global__ void __launch_bounds__(256, 2) k_sim() {
    extern __shared__ char smem[];
    const uint32_t sAu  = smem_u32(smem);
    const uint32_t sB1u = sAu + TILE_B;
    const uint32_t sB2u = sB1u + TILE_B;
    float* smRow = reinterpret_cast<float*>(smem + 3 * TILE_B);   // [2][128]
    float* smCol = smRow + 256;                                   // [4][128]

    const int tid  = threadIdx.x;
    const int wid  = tid >> 5;
    const int lane = tid & 31;

    // ---- decode pair p0 = 2*blockIdx (I, J); pair p1 is the consecutive one ----
    int I = 0, rem = 2 * blockIdx.x;
#pragma unroll 1
    for (; I < NBLK - 1 && rem >= NBLK - I; I++) rem -= NBLK - I;
    const int J = I + rem;

    int I2, J2;
    bool shareA;
    if (J < NBLK - 1) { I2 = I; J2 = J + 1; shareA = true; }
    else              { I2 = I + 1; J2 = I + 1; shareA = false; }  // diagonal: A==B

    // ---- load all three tiles via cp.async, one commit ----
#pragma unroll
    for (int i = 0; i < 8; i++) {
        int idx = tid + i * 256;
        int r   = idx >> 4;
        int kc  = (idx & 15) << 3;
        uint32_t so = (uint32_t)(r * SA + kc) * 2u;
        cp16(sAu  + so, &g_xn[(I  * 128 + r) * DIM + kc]);
        cp16(sB1u + so, &g_xn[(J  * 128 + r) * DIM + kc]);
        cp16(sB2u + so, &g_xn[(J2 * 128 + r) * DIM + kc]);
    }
    cp_commit();
    cp_wait0();
    __syncthreads();

    do_pair(sAu, sB1u, I, J, tid, wid, lane, smRow, smCol);
    do_pair(shareA ? sAu : sB2u, sB2u, I2, J2, tid, wid, lane, smRow, smCol);
}

// ---------------- kernel 3: final reduce ----------------
__global__ void k_final(float* out) {
    __shared__ float red[32];
    const int tid = threadIdx.x;
    float acc = 0.f;
    for (int r = tid; r < NROW; r += 1024)
        acc += lg2f(g_s[r]) - g_pair[r];   // pos_r in base-2 units
#pragma unroll
    for (int o = 16; o; o >>= 1) acc += __shfl_xor_sync(~0u, acc, o);
    if ((tid & 31) == 0) red[tid >> 5] = acc;
    __syncthreads();
    if (tid < 32) {
        float a = red[tid];
#pragma unroll
        for (int o = 16; o; o >>= 1) a += __shfl_xor_sync(~0u, a, o);
        if (tid == 0) out[0] = a * (0.6931471805599453f * 2048.0f); // ln2 * B/2
    }
}

// ---------------- launch ----------------
extern "C" void kernel_launch(void* const* d_in, const int* in_sizes, int n_in,
                              void* d_out, int out_size) {
    (void)in_sizes; (void)n_in; (void)out_size;
    const float* o1 = (const float*)d_in[0];
    const float* o2 = (const float*)d_in[1];

    k_norm<<<NROW / 8, 256>>>(o1, o2);

    static bool attr_set = false;
    if (!attr_set) {
        cudaFuncSetAttribute(k_sim, cudaFuncAttributeMaxDynamicSharedMemorySize, SMEM_BYTES);
        attr_set = true;
    }
    k_sim<<<NPAIR / 2, 256, SMEM_BYTES>>>();

    k_final<<<1, 1024>>>((float*)d_out);
}